// round 7
// baseline (speedup 1.0000x reference)
#include <cuda_runtime.h>
#include <cstdint>

#define NN 50000
#define EE 800000
#define CC 128
#define SCAN_BLOCKS 196   // ceil(50000/256)
#define PAD 132           // padded smem row stride (floats): conflict-free frags

// Scratch (static __device__ arrays — allocation-free)
__device__ float g_hs[(size_t)NN * CC];   // hs[j] = (x@W)[j] * dinv[j]
__device__ float g_dinv[NN];
__device__ int   g_deg[NN];               // edge-only in-degree (self excluded)
__device__ int   g_rowptr[NN + 1];
__device__ int   g_tmp[NN];               // per-block exclusive scan
__device__ int   g_bsum[256];             // per-block sums
__device__ int   g_fill[NN];              // fill cursors
__device__ int   g_srcidx[EE];            // CSR column (src) indices

// ---------------------------------------------------------------------------
__global__ void deg_init_kernel() {
    int i = blockIdx.x * blockDim.x + threadIdx.x;
    if (i < NN) g_deg[i] = 0;
}

__global__ void deg_count_kernel(const int* __restrict__ ei) {
    int e = blockIdx.x * blockDim.x + threadIdx.x;
    if (e < EE) atomicAdd(&g_deg[ei[EE + e]], 1);
}

// per-block exclusive scan of deg
__global__ void scan1_kernel() {
    __shared__ int s[256];
    int t = threadIdx.x;
    int i = blockIdx.x * 256 + t;
    int val = (i < NN) ? g_deg[i] : 0;
    s[t] = val;
    __syncthreads();
#pragma unroll
    for (int off = 1; off < 256; off <<= 1) {
        int v = (t >= off) ? s[t - off] : 0;
        __syncthreads();
        s[t] += v;
        __syncthreads();
    }
    if (i < NN) g_tmp[i] = s[t] - val;       // exclusive
    if (t == 255) g_bsum[blockIdx.x] = s[255];
}

// scan2+scan3 fused: each block warp-reduces its base from preceding block
// sums, then finalizes rowptr / fill / dinv.
__global__ void scan23_kernel() {
    __shared__ int sbase;
    int t = threadIdx.x;
    if (t < 32) {
        int sum = 0;
        for (int j = t; j < blockIdx.x; j += 32) sum += g_bsum[j];
#pragma unroll
        for (int off = 16; off > 0; off >>= 1)
            sum += __shfl_xor_sync(0xffffffffu, sum, off);
        if (t == 0) sbase = sum;
    }
    __syncthreads();
    int i = blockIdx.x * 256 + t;
    if (i < NN) {
        g_rowptr[i] = g_tmp[i] + sbase;
        g_fill[i] = 0;
        g_dinv[i] = rsqrtf((float)(g_deg[i] + 1));
    }
    if (i == 0) g_rowptr[NN] = EE;
}

// bucket edges into CSR (order within bucket irrelevant)
__global__ void fill_kernel(const int* __restrict__ ei) {
    int e = blockIdx.x * blockDim.x + threadIdx.x;
    if (e < EE) {
        int src = ei[e];
        int dst = ei[EE + e];
        int pos = atomicAdd(&g_fill[dst], 1);
        g_srcidx[g_rowptr[dst] + pos] = src;
    }
}

// ---------------------------------------------------------------------------
// GEMM via tf32 mma.sync.m16n8k8: hs = (x @ W) * dinv[row].
// Block: 256 threads (8 warps), 128 rows x 128 cols.
// Warp (rg = wid&3, cg = wid>>2): rows rg*32..+31 (2 A-tiles), cols cg*64 (8 n-tiles).
// smem: x tile [128][PAD] + W^T [128][PAD], both padded -> conflict-free frag LDS.
__global__ void gemm_tc_kernel(const float* __restrict__ x,
                               const float* __restrict__ w) {
    extern __shared__ float smem[];
    float* sx = smem;              // [128][PAD]
    float* sw = smem + 128 * PAD;  // W^T: [n(128)][PAD] over k

    const int row0 = blockIdx.x * 128;
    const int t = threadIdx.x;
    const int lane = t & 31;
    const int wid = t >> 5;
    const int gid = lane >> 2;     // 0..7
    const int tig = lane & 3;      // 0..3

    // stage x tile (coalesced float4; zero-pad rows >= NN)
    const float4* x4 = (const float4*)x;
    for (int i = t; i < 128 * 32; i += 256) {
        int r = i >> 5, c4 = i & 31;
        int row = row0 + r;
        float4 v = (row < NN) ? x4[(size_t)row * 32 + c4]
                              : make_float4(0.f, 0.f, 0.f, 0.f);
        *(float4*)(sx + r * PAD + c4 * 4) = v;
    }
    // stage W^T (read coalesced along n, scatter-store transpose)
    const float4* w4 = (const float4*)w;
    for (int i = t; i < 128 * 32; i += 256) {
        int k = i >> 5, c4 = i & 31;
        float4 v = w4[k * 32 + c4];
        sw[(c4 * 4 + 0) * PAD + k] = v.x;
        sw[(c4 * 4 + 1) * PAD + k] = v.y;
        sw[(c4 * 4 + 2) * PAD + k] = v.z;
        sw[(c4 * 4 + 3) * PAD + k] = v.w;
    }
    __syncthreads();

    const int r_base = (wid & 3) * 32;
    const int n_base = (wid >> 2) * 64;

    float acc[2][8][4] = {};

#pragma unroll 2
    for (int ks = 0; ks < 16; ks++) {
        int k0 = ks * 8;
        // A fragments for the 2 row tiles
        uint32_t a[2][4];
#pragma unroll
        for (int tt = 0; tt < 2; tt++) {
            const float* base = sx + (r_base + tt * 16 + gid) * PAD + k0 + tig;
            a[tt][0] = __float_as_uint(base[0]);
            a[tt][1] = __float_as_uint(base[8 * PAD]);
            a[tt][2] = __float_as_uint(base[4]);
            a[tt][3] = __float_as_uint(base[8 * PAD + 4]);
        }
#pragma unroll
        for (int j = 0; j < 8; j++) {
            const float* bb = sw + (n_base + j * 8 + gid) * PAD + k0 + tig;
            uint32_t b0 = __float_as_uint(bb[0]);
            uint32_t b1 = __float_as_uint(bb[4]);
#pragma unroll
            for (int tt = 0; tt < 2; tt++) {
                asm volatile(
                    "mma.sync.aligned.m16n8k8.row.col.f32.tf32.tf32.f32 "
                    "{%0,%1,%2,%3}, {%4,%5,%6,%7}, {%8,%9}, {%0,%1,%2,%3};"
                    : "+f"(acc[tt][j][0]), "+f"(acc[tt][j][1]),
                      "+f"(acc[tt][j][2]), "+f"(acc[tt][j][3])
                    : "r"(a[tt][0]), "r"(a[tt][1]), "r"(a[tt][2]), "r"(a[tt][3]),
                      "r"(b0), "r"(b1));
            }
        }
    }

    // epilogue: scale by dinv[row], write hs
#pragma unroll
    for (int tt = 0; tt < 2; tt++) {
        int rowA = row0 + r_base + tt * 16 + gid;
        int rowB = rowA + 8;
        float dA = (rowA < NN) ? g_dinv[rowA] : 0.f;
        float dB = (rowB < NN) ? g_dinv[rowB] : 0.f;
#pragma unroll
        for (int j = 0; j < 8; j++) {
            int n = n_base + j * 8 + 2 * tig;
            if (rowA < NN)
                *(float2*)(g_hs + (size_t)rowA * CC + n) =
                    make_float2(acc[tt][j][0] * dA, acc[tt][j][1] * dA);
            if (rowB < NN)
                *(float2*)(g_hs + (size_t)rowB * CC + n) =
                    make_float2(acc[tt][j][2] * dB, acc[tt][j][3] * dB);
        }
    }
}

// ---------------------------------------------------------------------------
// CSR gather: one warp per node; accumulate self + in-neighbors, fused epilogue.
__global__ void gather_kernel(float* __restrict__ out,
                              const float* __restrict__ bias) {
    int warp = (blockIdx.x * blockDim.x + threadIdx.x) >> 5;
    if (warp >= NN) return;
    int lane = threadIdx.x & 31;
    const float4* hs4 = (const float4*)g_hs;

    int start = g_rowptr[warp];
    int end   = g_rowptr[warp + 1];

    float4 acc = __ldg(&hs4[(size_t)warp * 32 + lane]);  // self-loop message

    for (int c = start; c < end; c += 32) {
        int n = min(32, end - c);
        int myidx = (c + lane < end) ? __ldg(&g_srcidx[c + lane]) : 0;
#pragma unroll 4
        for (int j = 0; j < n; j++) {
            int s = __shfl_sync(0xffffffffu, myidx, j);
            float4 v = __ldg(&hs4[(size_t)s * 32 + lane]);
            acc.x += v.x; acc.y += v.y; acc.z += v.z; acc.w += v.w;
        }
    }

    float d = g_dinv[warp];
    float4 b = ((const float4*)bias)[lane];
    float4 o;
    o.x = fmaxf(fmaf(acc.x, d, b.x), 0.f);
    o.y = fmaxf(fmaf(acc.y, d, b.y), 0.f);
    o.z = fmaxf(fmaf(acc.z, d, b.z), 0.f);
    o.w = fmaxf(fmaf(acc.w, d, b.w), 0.f);
    ((float4*)out)[(size_t)warp * 32 + lane] = o;
}

// ---------------------------------------------------------------------------
extern "C" void kernel_launch(void* const* d_in, const int* in_sizes, int n_in,
                              void* d_out, int out_size) {
    const float* x    = (const float*)d_in[0];   // [50000,128] f32
    const int*   ei   = (const int*)d_in[1];     // [2,800000] int32
    const float* w    = (const float*)d_in[2];   // [128,128] f32
    const float* bias = (const float*)d_in[3];   // [128] f32
    float* out = (float*)d_out;                  // [50000,128] f32
    (void)in_sizes; (void)n_in; (void)out_size;

    deg_init_kernel<<<(NN + 255) / 256, 256>>>();
    deg_count_kernel<<<(EE + 255) / 256, 256>>>(ei);
    scan1_kernel<<<SCAN_BLOCKS, 256>>>();
    scan23_kernel<<<SCAN_BLOCKS, 256>>>();
    fill_kernel<<<(EE + 255) / 256, 256>>>(ei);

    const int smem_bytes = 2 * 128 * PAD * sizeof(float);  // 132 KB
    cudaFuncSetAttribute(gemm_tc_kernel,
                         cudaFuncAttributeMaxDynamicSharedMemorySize, smem_bytes);
    gemm_tc_kernel<<<(NN + 127) / 128, 256, smem_bytes>>>(x, w);

    gather_kernel<<<(NN * 32 + 255) / 256, 256>>>(out, bias);
}